// round 1
// baseline (speedup 1.0000x reference)
#include <cuda_runtime.h>
#include <math_constants.h>

#define NTOK 4096      // B*S
#define DIM  1024
#define HEADS 16
#define HDIM 64
#define SEQ  2048
#define BATCH 2

// Scratch (allocation-free requirement -> __device__ globals)
__device__ float g_q[NTOK * DIM];
__device__ float g_k[NTOK * DIM];
__device__ float g_v[NTOK * DIM];
__device__ float g_ctx[NTOK * DIM];

// ---------------------------------------------------------------------------
// SGEMM: C[M,N] = A[M,K] @ W[K,N] + bias[N]   (all row-major fp32)
// 128x128 block tile, BK=8, 256 threads, 8x8 per thread (cols split 2x4 to
// keep shared-load bank conflicts at 2-way).
// ---------------------------------------------------------------------------
__global__ void __launch_bounds__(256) sgemm_bias_kernel(
    const float* __restrict__ A, const float* __restrict__ W,
    const float* __restrict__ bias, float* __restrict__ C,
    int M, int N, int K)
{
    __shared__ float As[8][132];   // [k][m], padded stride for transpose stores
    __shared__ float Bs[8][128];   // [k][n]

    const int tid  = threadIdx.x;
    const int brow = blockIdx.y * 128;
    const int bcol = blockIdx.x * 128;

    const int aRow = tid >> 1;          // 0..127
    const int aCol = (tid & 1) << 2;    // 0 or 4
    const int bRow = tid >> 5;          // 0..7
    const int bCol = (tid & 31) << 2;   // 0..124

    const int ty = tid >> 4;            // 0..15 -> rows ty*8..+7
    const int tx = tid & 15;            // 0..15 -> cols tx*4..+3 and 64+tx*4..+3

    float acc[8][8];
#pragma unroll
    for (int i = 0; i < 8; i++)
#pragma unroll
        for (int j = 0; j < 8; j++) acc[i][j] = 0.f;

    const float* Aptr = A + (size_t)(brow + aRow) * K + aCol;
    const float* Wptr = W + (size_t)bRow * N + bcol + bCol;

    for (int k0 = 0; k0 < K; k0 += 8) {
        float4 av = *reinterpret_cast<const float4*>(Aptr + k0);
        As[aCol + 0][aRow] = av.x;
        As[aCol + 1][aRow] = av.y;
        As[aCol + 2][aRow] = av.z;
        As[aCol + 3][aRow] = av.w;
        float4 wv = *reinterpret_cast<const float4*>(Wptr + (size_t)k0 * N);
        *reinterpret_cast<float4*>(&Bs[bRow][bCol]) = wv;
        __syncthreads();

#pragma unroll
        for (int kk = 0; kk < 8; kk++) {
            float ar[8], br[8];
#pragma unroll
            for (int i = 0; i < 8; i++) ar[i] = As[kk][ty * 8 + i];
#pragma unroll
            for (int j = 0; j < 4; j++) {
                br[j]     = Bs[kk][tx * 4 + j];
                br[4 + j] = Bs[kk][64 + tx * 4 + j];
            }
#pragma unroll
            for (int i = 0; i < 8; i++)
#pragma unroll
                for (int j = 0; j < 8; j++) acc[i][j] += ar[i] * br[j];
        }
        __syncthreads();
    }

#pragma unroll
    for (int i = 0; i < 8; i++) {
        const int r  = brow + ty * 8 + i;
        const int c0 = bcol + tx * 4;
        const int c1 = c0 + 64;
        float4 o0, o1;
        o0.x = acc[i][0] + bias[c0 + 0];
        o0.y = acc[i][1] + bias[c0 + 1];
        o0.z = acc[i][2] + bias[c0 + 2];
        o0.w = acc[i][3] + bias[c0 + 3];
        o1.x = acc[i][4] + bias[c1 + 0];
        o1.y = acc[i][5] + bias[c1 + 1];
        o1.z = acc[i][6] + bias[c1 + 2];
        o1.w = acc[i][7] + bias[c1 + 3];
        *reinterpret_cast<float4*>(&C[(size_t)r * N + c0]) = o0;
        *reinterpret_cast<float4*>(&C[(size_t)r * N + c1]) = o1;
    }
}

// ---------------------------------------------------------------------------
// Flash attention: per CTA one (b, h, 64-query tile). Online softmax over
// 32 key tiles of 64. 256 threads, per-thread 4x4 register tiles.
// Shared: sQ[64][64], sKP[64][65] (K tile, reused for P), sV[64][64].
// ---------------------------------------------------------------------------
#define SMEM_ATTN_FLOATS (64 * 64 + 64 * 65 + 64 * 64)
#define SMEM_ATTN_BYTES  (SMEM_ATTN_FLOATS * 4)

__global__ void __launch_bounds__(256) attn_kernel(
    const float* __restrict__ Q, const float* __restrict__ K,
    const float* __restrict__ V, float* __restrict__ O)
{
    extern __shared__ float sm[];
    float* sQ  = sm;                       // [64][64] row-major
    float* sKP = sm + 64 * 64;             // [64][65] K tile / P tile
    float* sV  = sm + 64 * 64 + 64 * 65;   // [64][64] row-major

    const int tid = threadIdx.x;
    const int ty  = tid >> 4;   // 0..15 -> score/O rows ty*4..+3
    const int tx  = tid & 15;   // 0..15 -> score cols / O cols tx*4..+3

    const int q0 = blockIdx.x * 64;
    const int h  = blockIdx.y;
    const int b  = blockIdx.z;
    const size_t rowbase = (size_t)b * SEQ;
    const int colbase = h * HDIM;

    // Load Q tile (64 rows x 64 cols)
#pragma unroll
    for (int it = 0; it < 4; it++) {
        int idx = it * 256 + tid;          // float4 index
        int r   = idx >> 4;
        int d4  = (idx & 15) << 2;
        float4 v = *reinterpret_cast<const float4*>(
            &Q[(rowbase + q0 + r) * DIM + colbase + d4]);
        *reinterpret_cast<float4*>(&sQ[r * 64 + d4]) = v;
    }

    float m[4], l[4], accO[4][4];
#pragma unroll
    for (int i = 0; i < 4; i++) {
        m[i] = -CUDART_INF_F;
        l[i] = 0.f;
#pragma unroll
        for (int j = 0; j < 4; j++) accO[i][j] = 0.f;
    }

    for (int t0 = 0; t0 < SEQ; t0 += 64) {
        __syncthreads();   // prior-iteration readers of sKP/sV are done

        // Load K tile (scalar stores into stride-65) and V tile (float4)
#pragma unroll
        for (int it = 0; it < 4; it++) {
            int idx = it * 256 + tid;
            int r   = idx >> 4;
            int d4  = (idx & 15) << 2;
            float4 kv = *reinterpret_cast<const float4*>(
                &K[(rowbase + t0 + r) * DIM + colbase + d4]);
            sKP[r * 65 + d4 + 0] = kv.x;
            sKP[r * 65 + d4 + 1] = kv.y;
            sKP[r * 65 + d4 + 2] = kv.z;
            sKP[r * 65 + d4 + 3] = kv.w;
            float4 vv = *reinterpret_cast<const float4*>(
                &V[(rowbase + t0 + r) * DIM + colbase + d4]);
            *reinterpret_cast<float4*>(&sV[r * 64 + d4]) = vv;
        }
        __syncthreads();

        // S = (Q @ K^T) * 1/sqrt(64)
        float s[4][4];
#pragma unroll
        for (int i = 0; i < 4; i++)
#pragma unroll
            for (int j = 0; j < 4; j++) s[i][j] = 0.f;

#pragma unroll 4
        for (int d = 0; d < 64; d++) {
            float ar[4], br[4];
#pragma unroll
            for (int i = 0; i < 4; i++) ar[i] = sQ[(ty * 4 + i) * 64 + d];
#pragma unroll
            for (int j = 0; j < 4; j++) br[j] = sKP[(tx * 4 + j) * 65 + d];
#pragma unroll
            for (int i = 0; i < 4; i++)
#pragma unroll
                for (int j = 0; j < 4; j++) s[i][j] += ar[i] * br[j];
        }

        // Online softmax update (row stats shared across the 16 tx lanes)
        float p[4][4];
#pragma unroll
        for (int i = 0; i < 4; i++) {
            float mt = fmaxf(fmaxf(s[i][0], s[i][1]), fmaxf(s[i][2], s[i][3])) * 0.125f;
#pragma unroll
            for (int off = 8; off >= 1; off >>= 1)
                mt = fmaxf(mt, __shfl_xor_sync(0xffffffffu, mt, off));
            float mn = fmaxf(m[i], mt);
            float al = __expf(m[i] - mn);
            m[i] = mn;
            float lt = 0.f;
#pragma unroll
            for (int j = 0; j < 4; j++) {
                p[i][j] = __expf(s[i][j] * 0.125f - mn);
                lt += p[i][j];
            }
#pragma unroll
            for (int off = 8; off >= 1; off >>= 1)
                lt += __shfl_xor_sync(0xffffffffu, lt, off);
            l[i] = l[i] * al + lt;
#pragma unroll
            for (int j = 0; j < 4; j++) accO[i][j] *= al;
        }

        __syncthreads();   // all QK reads of sKP done before overwrite with P
#pragma unroll
        for (int i = 0; i < 4; i++)
#pragma unroll
            for (int j = 0; j < 4; j++)
                sKP[(ty * 4 + i) * 65 + tx * 4 + j] = p[i][j];
        __syncthreads();

        // O += P @ V
#pragma unroll 4
        for (int j = 0; j < 64; j++) {
            float pr[4], vr[4];
#pragma unroll
            for (int i = 0; i < 4; i++) pr[i] = sKP[(ty * 4 + i) * 65 + j];
#pragma unroll
            for (int c = 0; c < 4; c++) vr[c] = sV[j * 64 + tx * 4 + c];
#pragma unroll
            for (int i = 0; i < 4; i++)
#pragma unroll
                for (int c = 0; c < 4; c++) accO[i][c] += pr[i] * vr[c];
        }
    }

    // Normalize and write ctx (layout [B,S,H*Dh] so the final GEMM is dense)
#pragma unroll
    for (int i = 0; i < 4; i++) {
        float inv = 1.f / l[i];
        float4 o;
        o.x = accO[i][0] * inv;
        o.y = accO[i][1] * inv;
        o.z = accO[i][2] * inv;
        o.w = accO[i][3] * inv;
        *reinterpret_cast<float4*>(
            &O[(rowbase + q0 + ty * 4 + i) * DIM + colbase + tx * 4]) = o;
    }
}

// ---------------------------------------------------------------------------
extern "C" void kernel_launch(void* const* d_in, const int* in_sizes, int n_in,
                              void* d_out, int out_size)
{
    const float* x  = (const float*)d_in[0];
    const float* Wq = (const float*)d_in[1];
    const float* bq = (const float*)d_in[2];
    const float* Wk = (const float*)d_in[3];
    const float* bk = (const float*)d_in[4];
    const float* Wv = (const float*)d_in[5];
    const float* bv = (const float*)d_in[6];
    const float* Wo = (const float*)d_in[7];
    const float* bo = (const float*)d_in[8];
    float* out = (float*)d_out;

    float *q, *k, *v, *ctx;
    cudaGetSymbolAddress((void**)&q, g_q);
    cudaGetSymbolAddress((void**)&k, g_k);
    cudaGetSymbolAddress((void**)&v, g_v);
    cudaGetSymbolAddress((void**)&ctx, g_ctx);

    dim3 gg(DIM / 128, NTOK / 128);
    sgemm_bias_kernel<<<gg, 256>>>(x, Wq, bq, q, NTOK, DIM, DIM);
    sgemm_bias_kernel<<<gg, 256>>>(x, Wk, bk, k, NTOK, DIM, DIM);
    sgemm_bias_kernel<<<gg, 256>>>(x, Wv, bv, v, NTOK, DIM, DIM);

    cudaFuncSetAttribute(attn_kernel,
                         cudaFuncAttributeMaxDynamicSharedMemorySize,
                         SMEM_ATTN_BYTES);
    attn_kernel<<<dim3(SEQ / 64, HEADS, BATCH), 256, SMEM_ATTN_BYTES>>>(q, k, v, ctx);

    sgemm_bias_kernel<<<gg, 256>>>(ctx, Wo, bo, out, NTOK, DIM, DIM);
}

// round 3
// speedup vs baseline: 1.4095x; 1.4095x over previous
#include <cuda_runtime.h>
#include <math_constants.h>
#include <cstdint>

#define NTOK 4096      // B*S
#define DIM  1024
#define HEADS 16
#define HDIM 64
#define SEQ  2048
#define BATCH 2

// Scratch (allocation-free requirement -> __device__ globals)
__device__ float g_q[NTOK * DIM];
__device__ float g_k[NTOK * DIM];
__device__ float g_v[NTOK * DIM];
__device__ float g_ctx[NTOK * DIM];
__device__ float g_xr[NTOK * DIM];        // tf32-rounded x
__device__ float g_wt[4 * DIM * DIM];     // transposed+rounded Wq,Wk,Wv,Wo

// ===========================================================================
// Helpers
// ===========================================================================
__device__ __forceinline__ float f2tf32(float f) {
    uint32_t u;
    asm("cvt.rna.tf32.f32 %0, %1;" : "=r"(u) : "f"(f));
    return __uint_as_float(u);
}

#define CP_ASYNC16(smem_addr, gmem_ptr) \
    asm volatile("cp.async.cg.shared.global [%0], [%1], 16;" \
                 :: "r"((uint32_t)(smem_addr)), "l"(gmem_ptr) : "memory")
#define CP_COMMIT() asm volatile("cp.async.commit_group;" ::: "memory")
#define CP_WAIT(n)  asm volatile("cp.async.wait_group %0;" :: "n"(n) : "memory")

__device__ __forceinline__ uint32_t smem_u32(const void* p) {
    uint32_t a;
    asm("{ .reg .u64 t; cvta.to.shared.u64 t, %1; cvt.u32.u64 %0, t; }"
        : "=r"(a) : "l"(p));
    return a;
}

// mma.sync m16n8k8 tf32: D(16x8,f32) += A(16x8,tf32,row) * B(8x8,tf32,col)
__device__ __forceinline__ void mma_tf32(
    float* d, const uint32_t* a, const uint32_t* b)
{
    asm volatile(
        "mma.sync.aligned.m16n8k8.row.col.f32.tf32.tf32.f32 "
        "{%0,%1,%2,%3}, {%4,%5,%6,%7}, {%8,%9}, {%0,%1,%2,%3};"
        : "+f"(d[0]), "+f"(d[1]), "+f"(d[2]), "+f"(d[3])
        : "r"(a[0]), "r"(a[1]), "r"(a[2]), "r"(a[3]),
          "r"(b[0]), "r"(b[1]));
}

// ===========================================================================
// tf32 mma.sync GEMM: C[4096,1024] = A[4096,1024] @ Bt[1024,1024]^T + bias
//  A row-major [M][K];  Bt row-major [N][K] (pre-transposed W).
//  CTA tile 128x128, BK=32, 8 warps (4x2), warp tile 32x64, 2-stage cp.async.
//  Smem stride 36 floats -> conflict-free fragment loads ((4g+t)%32 distinct).
// ===========================================================================
#define GK 1024
#define GN 1024
#define BK 32
#define G_NT (GK / BK)          // 32 k-tiles
#define SASTRIDE 36             // floats per smem row
#define STAGE_FLOATS (128 * SASTRIDE)           // one operand, one stage
#define GEMM_SMEM_BYTES (4 * STAGE_FLOATS * 4)  // A0,A1,B0,B1 = 73728 B

__global__ void __launch_bounds__(256) gemm_mma_kernel(
    const float* __restrict__ A, const float* __restrict__ Bt,
    const float* __restrict__ bias, float* __restrict__ C)
{
    extern __shared__ __align__(16) float sm[];
    float* sA[2] = { sm,                  sm + STAGE_FLOATS };
    float* sB[2] = { sm + 2 * STAGE_FLOATS, sm + 3 * STAGE_FLOATS };

    const int tid  = threadIdx.x;
    const int wid  = tid >> 5;
    const int lane = tid & 31;
    const int g    = lane >> 2;   // group id 0..7
    const int t    = lane & 3;    // thread-in-group 0..3

    const int wm = wid >> 1;      // 0..3 -> warp rows wm*32
    const int wn = wid & 1;       // 0..1 -> warp cols wn*64

    const int brow = blockIdx.y * 128;
    const int bcol = blockIdx.x * 128;

    const uint32_t sAu[2] = { smem_u32(sA[0]), smem_u32(sA[1]) };
    const uint32_t sBu[2] = { smem_u32(sB[0]), smem_u32(sB[1]) };

    // per-thread gmem source: 4 chunks per operand per stage
    // chunk idx = tid + i*256 (i<4): r = idx>>3 (0..127), c = idx&7
    const int ldr = tid >> 3;          // base row (tid part)
    const int ldc = tid & 7;           // chunk col 0..7 (16B units)

    const float* Asrc = A  + (size_t)(brow + ldr) * GK + ldc * 4;
    const float* Bsrc = Bt + (size_t)(bcol + ldr) * GK + ldc * 4;

    auto load_stage = [&](int s, int k0) {
#pragma unroll
        for (int i = 0; i < 4; i++) {
            int r = ldr + i * 32;
            uint32_t off = (uint32_t)(r * SASTRIDE + ldc * 4) * 4u;
            CP_ASYNC16(sAu[s] + off, Asrc + (size_t)(i * 32) * GK + k0);
            CP_ASYNC16(sBu[s] + off, Bsrc + (size_t)(i * 32) * GK + k0);
        }
        CP_COMMIT();
    };

    float acc[2][8][4];
#pragma unroll
    for (int mi = 0; mi < 2; mi++)
#pragma unroll
        for (int ni = 0; ni < 8; ni++)
#pragma unroll
            for (int c = 0; c < 4; c++) acc[mi][ni][c] = 0.f;

    load_stage(0, 0);

    for (int kt = 0; kt < G_NT; ++kt) {
        const int cur = kt & 1;
        if (kt + 1 < G_NT) { load_stage(cur ^ 1, (kt + 1) * BK); CP_WAIT(1); }
        else               { CP_WAIT(0); }
        __syncthreads();

        const float* a_s = sA[cur];
        const float* b_s = sB[cur];

#pragma unroll
        for (int ks = 0; ks < 4; ks++) {
            const int k0 = ks * 8;
            uint32_t af[2][4];
#pragma unroll
            for (int mi = 0; mi < 2; mi++) {
                const int row = wm * 32 + mi * 16;
                af[mi][0] = __float_as_uint(a_s[(row + g)     * SASTRIDE + k0 + t]);
                af[mi][1] = __float_as_uint(a_s[(row + g + 8) * SASTRIDE + k0 + t]);
                af[mi][2] = __float_as_uint(a_s[(row + g)     * SASTRIDE + k0 + t + 4]);
                af[mi][3] = __float_as_uint(a_s[(row + g + 8) * SASTRIDE + k0 + t + 4]);
            }
            uint32_t bf[8][2];
#pragma unroll
            for (int ni = 0; ni < 8; ni++) {
                const int n = wn * 64 + ni * 8 + g;
                bf[ni][0] = __float_as_uint(b_s[n * SASTRIDE + k0 + t]);
                bf[ni][1] = __float_as_uint(b_s[n * SASTRIDE + k0 + t + 4]);
            }
#pragma unroll
            for (int mi = 0; mi < 2; mi++)
#pragma unroll
                for (int ni = 0; ni < 8; ni++)
                    mma_tf32(acc[mi][ni], af[mi], bf[ni]);
        }
        __syncthreads();
    }

    // Epilogue: bias + store (float2 per accum pair)
#pragma unroll
    for (int ni = 0; ni < 8; ni++) {
        const int col = bcol + wn * 64 + ni * 8 + t * 2;
        const float2 bv = *reinterpret_cast<const float2*>(&bias[col]);
#pragma unroll
        for (int mi = 0; mi < 2; mi++) {
            const int r0 = brow + wm * 32 + mi * 16 + g;
            float2 v0, v1;
            v0.x = acc[mi][ni][0] + bv.x;
            v0.y = acc[mi][ni][1] + bv.y;
            v1.x = acc[mi][ni][2] + bv.x;
            v1.y = acc[mi][ni][3] + bv.y;
            *reinterpret_cast<float2*>(&C[(size_t)r0 * GN + col])       = v0;
            *reinterpret_cast<float2*>(&C[(size_t)(r0 + 8) * GN + col]) = v1;
        }
    }
}

// ===========================================================================
// Weight transpose + tf32 round: Wt[n][k] = rna(W[k][n]),  1024x1024
// ===========================================================================
__global__ void transpose_round_kernel(const float* __restrict__ W,
                                       float* __restrict__ Wt)
{
    __shared__ float t[32][33];
    int n = blockIdx.x * 32 + threadIdx.x;
    int k = blockIdx.y * 32 + threadIdx.y;
#pragma unroll
    for (int j = 0; j < 32; j += 8)
        t[threadIdx.y + j][threadIdx.x] = W[(size_t)(k + j) * DIM + n];
    __syncthreads();
    int ko = blockIdx.y * 32 + threadIdx.x;
    int no = blockIdx.x * 32 + threadIdx.y;
#pragma unroll
    for (int j = 0; j < 32; j += 8)
        Wt[(size_t)(no + j) * DIM + ko] = f2tf32(t[threadIdx.x][threadIdx.y + j]);
}

// tf32-round a big fp32 array (float4)
__global__ void round_tf32_kernel(const float4* __restrict__ in,
                                  float4* __restrict__ out, int n4)
{
    int i = blockIdx.x * blockDim.x + threadIdx.x;
    if (i < n4) {
        float4 v = in[i];
        v.x = f2tf32(v.x); v.y = f2tf32(v.y);
        v.z = f2tf32(v.z); v.w = f2tf32(v.w);
        out[i] = v;
    }
}

// ===========================================================================
// Flash attention (fp32 CUDA-core path; ctx store tf32-rounded because it
// feeds the tf32 output GEMM). Conversion to mma.sync is next round.
// ===========================================================================
#define SMEM_ATTN_FLOATS (64 * 64 + 64 * 65 + 64 * 64)
#define SMEM_ATTN_BYTES  (SMEM_ATTN_FLOATS * 4)

__global__ void __launch_bounds__(256) attn_kernel(
    const float* __restrict__ Q, const float* __restrict__ K,
    const float* __restrict__ V, float* __restrict__ O)
{
    extern __shared__ float sm[];
    float* sQ  = sm;
    float* sKP = sm + 64 * 64;
    float* sV  = sm + 64 * 64 + 64 * 65;

    const int tid = threadIdx.x;
    const int ty  = tid >> 4;
    const int tx  = tid & 15;

    const int q0 = blockIdx.x * 64;
    const int h  = blockIdx.y;
    const int b  = blockIdx.z;
    const size_t rowbase = (size_t)b * SEQ;
    const int colbase = h * HDIM;

#pragma unroll
    for (int it = 0; it < 4; it++) {
        int idx = it * 256 + tid;
        int r   = idx >> 4;
        int d4  = (idx & 15) << 2;
        float4 v = *reinterpret_cast<const float4*>(
            &Q[(rowbase + q0 + r) * DIM + colbase + d4]);
        *reinterpret_cast<float4*>(&sQ[r * 64 + d4]) = v;
    }

    float m[4], l[4], accO[4][4];
#pragma unroll
    for (int i = 0; i < 4; i++) {
        m[i] = -CUDART_INF_F;
        l[i] = 0.f;
#pragma unroll
        for (int j = 0; j < 4; j++) accO[i][j] = 0.f;
    }

    for (int t0 = 0; t0 < SEQ; t0 += 64) {
        __syncthreads();
#pragma unroll
        for (int it = 0; it < 4; it++) {
            int idx = it * 256 + tid;
            int r   = idx >> 4;
            int d4  = (idx & 15) << 2;
            float4 kv = *reinterpret_cast<const float4*>(
                &K[(rowbase + t0 + r) * DIM + colbase + d4]);
            sKP[r * 65 + d4 + 0] = kv.x;
            sKP[r * 65 + d4 + 1] = kv.y;
            sKP[r * 65 + d4 + 2] = kv.z;
            sKP[r * 65 + d4 + 3] = kv.w;
            float4 vv = *reinterpret_cast<const float4*>(
                &V[(rowbase + t0 + r) * DIM + colbase + d4]);
            *reinterpret_cast<float4*>(&sV[r * 64 + d4]) = vv;
        }
        __syncthreads();

        float s[4][4];
#pragma unroll
        for (int i = 0; i < 4; i++)
#pragma unroll
            for (int j = 0; j < 4; j++) s[i][j] = 0.f;

#pragma unroll 4
        for (int d = 0; d < 64; d++) {
            float ar[4], br[4];
#pragma unroll
            for (int i = 0; i < 4; i++) ar[i] = sQ[(ty * 4 + i) * 64 + d];
#pragma unroll
            for (int j = 0; j < 4; j++) br[j] = sKP[(tx * 4 + j) * 65 + d];
#pragma unroll
            for (int i = 0; i < 4; i++)
#pragma unroll
                for (int j = 0; j < 4; j++) s[i][j] += ar[i] * br[j];
        }

        float p[4][4];
#pragma unroll
        for (int i = 0; i < 4; i++) {
            float mt = fmaxf(fmaxf(s[i][0], s[i][1]), fmaxf(s[i][2], s[i][3])) * 0.125f;
#pragma unroll
            for (int off = 8; off >= 1; off >>= 1)
                mt = fmaxf(mt, __shfl_xor_sync(0xffffffffu, mt, off));
            float mn = fmaxf(m[i], mt);
            float al = __expf(m[i] - mn);
            m[i] = mn;
            float lt = 0.f;
#pragma unroll
            for (int j = 0; j < 4; j++) {
                p[i][j] = __expf(s[i][j] * 0.125f - mn);
                lt += p[i][j];
            }
#pragma unroll
            for (int off = 8; off >= 1; off >>= 1)
                lt += __shfl_xor_sync(0xffffffffu, lt, off);
            l[i] = l[i] * al + lt;
#pragma unroll
            for (int j = 0; j < 4; j++) accO[i][j] *= al;
        }

        __syncthreads();
#pragma unroll
        for (int i = 0; i < 4; i++)
#pragma unroll
            for (int j = 0; j < 4; j++)
                sKP[(ty * 4 + i) * 65 + tx * 4 + j] = p[i][j];
        __syncthreads();

#pragma unroll 4
        for (int j = 0; j < 64; j++) {
            float pr[4], vr[4];
#pragma unroll
            for (int i = 0; i < 4; i++) pr[i] = sKP[(ty * 4 + i) * 65 + j];
#pragma unroll
            for (int c = 0; c < 4; c++) vr[c] = sV[j * 64 + tx * 4 + c];
#pragma unroll
            for (int i = 0; i < 4; i++)
#pragma unroll
                for (int c = 0; c < 4; c++) accO[i][c] += pr[i] * vr[c];
        }
    }

#pragma unroll
    for (int i = 0; i < 4; i++) {
        float inv = 1.f / l[i];
        float4 o;
        o.x = f2tf32(accO[i][0] * inv);
        o.y = f2tf32(accO[i][1] * inv);
        o.z = f2tf32(accO[i][2] * inv);
        o.w = f2tf32(accO[i][3] * inv);
        *reinterpret_cast<float4*>(
            &O[(rowbase + q0 + ty * 4 + i) * DIM + colbase + tx * 4]) = o;
    }
}

// ===========================================================================
extern "C" void kernel_launch(void* const* d_in, const int* in_sizes, int n_in,
                              void* d_out, int out_size)
{
    const float* x  = (const float*)d_in[0];
    const float* Wq = (const float*)d_in[1];
    const float* bq = (const float*)d_in[2];
    const float* Wk = (const float*)d_in[3];
    const float* bk = (const float*)d_in[4];
    const float* Wv = (const float*)d_in[5];
    const float* bv = (const float*)d_in[6];
    const float* Wo = (const float*)d_in[7];
    const float* bo = (const float*)d_in[8];
    float* out = (float*)d_out;

    float *q, *k, *v, *ctx, *xr, *wt;
    cudaGetSymbolAddress((void**)&q,   g_q);
    cudaGetSymbolAddress((void**)&k,   g_k);
    cudaGetSymbolAddress((void**)&v,   g_v);
    cudaGetSymbolAddress((void**)&ctx, g_ctx);
    cudaGetSymbolAddress((void**)&xr,  g_xr);
    cudaGetSymbolAddress((void**)&wt,  g_wt);
    float* wtq = wt;
    float* wtk = wt + DIM * DIM;
    float* wtv = wt + 2 * DIM * DIM;
    float* wto = wt + 3 * DIM * DIM;

    // 1) round x to tf32
    {
        int n4 = NTOK * DIM / 4;
        round_tf32_kernel<<<(n4 + 255) / 256, 256>>>(
            (const float4*)x, (float4*)xr, n4);
    }
    // 2) transpose + round weights
    {
        dim3 tb(32, 8), tg(DIM / 32, DIM / 32);
        transpose_round_kernel<<<tg, tb>>>(Wq, wtq);
        transpose_round_kernel<<<tg, tb>>>(Wk, wtk);
        transpose_round_kernel<<<tg, tb>>>(Wv, wtv);
        transpose_round_kernel<<<tg, tb>>>(Wo, wto);
    }

    // 3) QKV projections (mma.sync tf32)
    cudaFuncSetAttribute(gemm_mma_kernel,
                         cudaFuncAttributeMaxDynamicSharedMemorySize,
                         GEMM_SMEM_BYTES);
    dim3 gg(GN / 128, NTOK / 128);
    gemm_mma_kernel<<<gg, 256, GEMM_SMEM_BYTES>>>(xr, wtq, bq, q);
    gemm_mma_kernel<<<gg, 256, GEMM_SMEM_BYTES>>>(xr, wtk, bk, k);
    gemm_mma_kernel<<<gg, 256, GEMM_SMEM_BYTES>>>(xr, wtv, bv, v);

    // 4) attention
    cudaFuncSetAttribute(attn_kernel,
                         cudaFuncAttributeMaxDynamicSharedMemorySize,
                         SMEM_ATTN_BYTES);
    attn_kernel<<<dim3(SEQ / 64, HEADS, BATCH), 256, SMEM_ATTN_BYTES>>>(q, k, v, ctx);

    // 5) output projection
    gemm_mma_kernel<<<gg, 256, GEMM_SMEM_BYTES>>>(ctx, wto, bo, out);
}

// round 4
// speedup vs baseline: 3.1186x; 2.2126x over previous
#include <cuda_runtime.h>
#include <math_constants.h>
#include <cstdint>

#define NTOK 4096      // B*S
#define DIM  1024
#define HEADS 16
#define HDIM 64
#define SEQ  2048
#define BATCH 2

// Scratch (allocation-free requirement -> __device__ globals)
__device__ float g_q[NTOK * DIM];
__device__ float g_k[NTOK * DIM];
__device__ float g_v[NTOK * DIM];
__device__ float g_vt[NTOK * DIM];        // V transposed: [B][H][HDIM][SEQ]
__device__ float g_ctx[NTOK * DIM];
__device__ float g_xr[NTOK * DIM];        // tf32-rounded x
__device__ float g_wt[4 * DIM * DIM];     // transposed+rounded Wq,Wk,Wv,Wo

// ===========================================================================
// Helpers
// ===========================================================================
__device__ __forceinline__ float f2tf32(float f) {
    uint32_t u;
    asm("cvt.rna.tf32.f32 %0, %1;" : "=r"(u) : "f"(f));
    return __uint_as_float(u);
}

__device__ __forceinline__ float ex2f(float x) {
    float y;
    asm("ex2.approx.ftz.f32 %0, %1;" : "=f"(y) : "f"(x));
    return y;
}

#define CP_ASYNC16(smem_addr, gmem_ptr) \
    asm volatile("cp.async.cg.shared.global [%0], [%1], 16;" \
                 :: "r"((uint32_t)(smem_addr)), "l"(gmem_ptr) : "memory")
#define CP_COMMIT() asm volatile("cp.async.commit_group;" ::: "memory")
#define CP_WAIT(n)  asm volatile("cp.async.wait_group %0;" :: "n"(n) : "memory")

__device__ __forceinline__ uint32_t smem_u32(const void* p) {
    uint32_t a;
    asm("{ .reg .u64 t; cvta.to.shared.u64 t, %1; cvt.u32.u64 %0, t; }"
        : "=r"(a) : "l"(p));
    return a;
}

// mma.sync m16n8k8 tf32: D(16x8,f32) += A(16x8,tf32,row) * B(8x8,tf32,col)
__device__ __forceinline__ void mma_tf32(
    float* d, const uint32_t* a, const uint32_t* b)
{
    asm volatile(
        "mma.sync.aligned.m16n8k8.row.col.f32.tf32.tf32.f32 "
        "{%0,%1,%2,%3}, {%4,%5,%6,%7}, {%8,%9}, {%0,%1,%2,%3};"
        : "+f"(d[0]), "+f"(d[1]), "+f"(d[2]), "+f"(d[3])
        : "r"(a[0]), "r"(a[1]), "r"(a[2]), "r"(a[3]),
          "r"(b[0]), "r"(b[1]));
}

// ===========================================================================
// tf32 mma.sync GEMM: C[4096,1024] = A[4096,1024] @ Bt[1024,1024]^T + bias
//  round_out: tf32-round the outputs (for tensors feeding further tf32 mma).
// ===========================================================================
#define GK 1024
#define GN 1024
#define BK 32
#define G_NT (GK / BK)
#define SASTRIDE 36
#define STAGE_FLOATS (128 * SASTRIDE)
#define GEMM_SMEM_BYTES (4 * STAGE_FLOATS * 4)

__global__ void __launch_bounds__(256) gemm_mma_kernel(
    const float* __restrict__ A, const float* __restrict__ Bt,
    const float* __restrict__ bias, float* __restrict__ C, int round_out)
{
    extern __shared__ __align__(16) float sm[];
    float* sA[2] = { sm,                    sm + STAGE_FLOATS };
    float* sB[2] = { sm + 2 * STAGE_FLOATS, sm + 3 * STAGE_FLOATS };

    const int tid  = threadIdx.x;
    const int wid  = tid >> 5;
    const int lane = tid & 31;
    const int g    = lane >> 2;
    const int t    = lane & 3;

    const int wm = wid >> 1;
    const int wn = wid & 1;

    const int brow = blockIdx.y * 128;
    const int bcol = blockIdx.x * 128;

    const uint32_t sAu[2] = { smem_u32(sA[0]), smem_u32(sA[1]) };
    const uint32_t sBu[2] = { smem_u32(sB[0]), smem_u32(sB[1]) };

    const int ldr = tid >> 3;
    const int ldc = tid & 7;

    const float* Asrc = A  + (size_t)(brow + ldr) * GK + ldc * 4;
    const float* Bsrc = Bt + (size_t)(bcol + ldr) * GK + ldc * 4;

    auto load_stage = [&](int s, int k0) {
#pragma unroll
        for (int i = 0; i < 4; i++) {
            int r = ldr + i * 32;
            uint32_t off = (uint32_t)(r * SASTRIDE + ldc * 4) * 4u;
            CP_ASYNC16(sAu[s] + off, Asrc + (size_t)(i * 32) * GK + k0);
            CP_ASYNC16(sBu[s] + off, Bsrc + (size_t)(i * 32) * GK + k0);
        }
        CP_COMMIT();
    };

    float acc[2][8][4];
#pragma unroll
    for (int mi = 0; mi < 2; mi++)
#pragma unroll
        for (int ni = 0; ni < 8; ni++)
#pragma unroll
            for (int c = 0; c < 4; c++) acc[mi][ni][c] = 0.f;

    load_stage(0, 0);

    for (int kt = 0; kt < G_NT; ++kt) {
        const int cur = kt & 1;
        if (kt + 1 < G_NT) { load_stage(cur ^ 1, (kt + 1) * BK); CP_WAIT(1); }
        else               { CP_WAIT(0); }
        __syncthreads();

        const float* a_s = sA[cur];
        const float* b_s = sB[cur];

#pragma unroll
        for (int ks = 0; ks < 4; ks++) {
            const int k0 = ks * 8;
            uint32_t af[2][4];
#pragma unroll
            for (int mi = 0; mi < 2; mi++) {
                const int row = wm * 32 + mi * 16;
                af[mi][0] = __float_as_uint(a_s[(row + g)     * SASTRIDE + k0 + t]);
                af[mi][1] = __float_as_uint(a_s[(row + g + 8) * SASTRIDE + k0 + t]);
                af[mi][2] = __float_as_uint(a_s[(row + g)     * SASTRIDE + k0 + t + 4]);
                af[mi][3] = __float_as_uint(a_s[(row + g + 8) * SASTRIDE + k0 + t + 4]);
            }
            uint32_t bf[8][2];
#pragma unroll
            for (int ni = 0; ni < 8; ni++) {
                const int n = wn * 64 + ni * 8 + g;
                bf[ni][0] = __float_as_uint(b_s[n * SASTRIDE + k0 + t]);
                bf[ni][1] = __float_as_uint(b_s[n * SASTRIDE + k0 + t + 4]);
            }
#pragma unroll
            for (int mi = 0; mi < 2; mi++)
#pragma unroll
                for (int ni = 0; ni < 8; ni++)
                    mma_tf32(acc[mi][ni], af[mi], bf[ni]);
        }
        __syncthreads();
    }

#pragma unroll
    for (int ni = 0; ni < 8; ni++) {
        const int col = bcol + wn * 64 + ni * 8 + t * 2;
        const float2 bv = *reinterpret_cast<const float2*>(&bias[col]);
#pragma unroll
        for (int mi = 0; mi < 2; mi++) {
            const int r0 = brow + wm * 32 + mi * 16 + g;
            float2 v0, v1;
            v0.x = acc[mi][ni][0] + bv.x;
            v0.y = acc[mi][ni][1] + bv.y;
            v1.x = acc[mi][ni][2] + bv.x;
            v1.y = acc[mi][ni][3] + bv.y;
            if (round_out) {
                v0.x = f2tf32(v0.x); v0.y = f2tf32(v0.y);
                v1.x = f2tf32(v1.x); v1.y = f2tf32(v1.y);
            }
            *reinterpret_cast<float2*>(&C[(size_t)r0 * GN + col])       = v0;
            *reinterpret_cast<float2*>(&C[(size_t)(r0 + 8) * GN + col]) = v1;
        }
    }
}

// ===========================================================================
// Weight transpose + tf32 round: Wt[n][k] = rna(W[k][n]),  1024x1024
// ===========================================================================
__global__ void transpose_round_kernel(const float* __restrict__ W,
                                       float* __restrict__ Wt)
{
    __shared__ float t[32][33];
    int n = blockIdx.x * 32 + threadIdx.x;
    int k = blockIdx.y * 32 + threadIdx.y;
#pragma unroll
    for (int j = 0; j < 32; j += 8)
        t[threadIdx.y + j][threadIdx.x] = W[(size_t)(k + j) * DIM + n];
    __syncthreads();
    int ko = blockIdx.y * 32 + threadIdx.x;
    int no = blockIdx.x * 32 + threadIdx.y;
#pragma unroll
    for (int j = 0; j < 32; j += 8)
        Wt[(size_t)(no + j) * DIM + ko] = f2tf32(t[threadIdx.x][threadIdx.y + j]);
}

// V transpose: v [B,S,H*64] -> vt [B,H,64,SEQ]
__global__ void vt_transpose_kernel(const float* __restrict__ v,
                                    float* __restrict__ vt)
{
    __shared__ float t[32][33];
    const int bh = blockIdx.z;                  // b*16 + h
    const int b  = bh >> 4;
    const int h  = bh & 15;
    const int s0 = blockIdx.x * 32;
    const int d0 = blockIdx.y * 32;
#pragma unroll
    for (int j = 0; j < 32; j += 8)
        t[threadIdx.y + j][threadIdx.x] =
            v[(size_t)(b * SEQ + s0 + threadIdx.y + j) * DIM + h * HDIM + d0 + threadIdx.x];
    __syncthreads();
#pragma unroll
    for (int j = 0; j < 32; j += 8)
        vt[((size_t)bh * HDIM + d0 + threadIdx.y + j) * SEQ + s0 + threadIdx.x] =
            t[threadIdx.x][threadIdx.y + j];
}

// tf32-round a big fp32 array (float4)
__global__ void round_tf32_kernel(const float4* __restrict__ in,
                                  float4* __restrict__ out, int n4)
{
    int i = blockIdx.x * blockDim.x + threadIdx.x;
    if (i < n4) {
        float4 v = in[i];
        v.x = f2tf32(v.x); v.y = f2tf32(v.y);
        v.z = f2tf32(v.z); v.w = f2tf32(v.w);
        out[i] = v;
    }
}

// ===========================================================================
// Flash attention, mma.sync tf32.
//  Per CTA: 128 queries x one (b,h). 8 warps, warp = 16 query rows.
//  Tiles of 64 keys; online softmax in exp2 domain (scale folded into Q).
// ===========================================================================
#define ASTR 68   // smem row stride (floats), 68 % 32 == 4 -> conflict-free frags
#define ATTN_SMEM_FLOATS (128 * ASTR + 64 * ASTR + 64 * ASTR + 128 * ASTR)
#define ATTN_SMEM_BYTES  (ATTN_SMEM_FLOATS * 4)

__global__ void __launch_bounds__(256, 2) attn_mma_kernel(
    const float* __restrict__ Q, const float* __restrict__ K,
    const float* __restrict__ Vt, float* __restrict__ O)
{
    extern __shared__ __align__(16) float sm[];
    float* sQ  = sm;                        // [128][ASTR]
    float* sK  = sQ + 128 * ASTR;           // [64][ASTR]   keys x dh
    float* sVt = sK + 64 * ASTR;            // [64][ASTR]   dh x keys
    float* sP  = sVt + 64 * ASTR;           // [128][ASTR]

    const uint32_t sKu  = smem_u32(sK);
    const uint32_t sVtu = smem_u32(sVt);

    const int tid  = threadIdx.x;
    const int wid  = tid >> 5;
    const int lane = tid & 31;
    const int g    = lane >> 2;
    const int t    = lane & 3;
    const int wm   = wid * 16;              // warp's query-row base

    const int q0 = blockIdx.x * 128;
    const int h  = blockIdx.y;
    const int b  = blockIdx.z;
    const size_t rowbase = (size_t)b * SEQ;
    const int colbase = h * HDIM;
    const int bh = b * HEADS + h;

    const float cscale = 0.125f * 1.4426950408889634f;  // 1/sqrt(64) * log2(e)

    // ---- stage Q (scaled, tf32-rounded) ----
#pragma unroll
    for (int i = 0; i < 8; i++) {
        int idx = tid + i * 256;            // float4 chunk id, 2048 total
        int r   = idx >> 4;
        int d4  = (idx & 15) << 2;
        float4 v = *reinterpret_cast<const float4*>(
            &Q[(rowbase + q0 + r) * DIM + colbase + d4]);
        sQ[r * ASTR + d4 + 0] = f2tf32(v.x * cscale);
        sQ[r * ASTR + d4 + 1] = f2tf32(v.y * cscale);
        sQ[r * ASTR + d4 + 2] = f2tf32(v.z * cscale);
        sQ[r * ASTR + d4 + 3] = f2tf32(v.w * cscale);
    }

    float m0 = -CUDART_INF_F, m1 = -CUDART_INF_F;
    float l0 = 0.f, l1 = 0.f;
    float accO[8][4];
#pragma unroll
    for (int ni = 0; ni < 8; ni++)
#pragma unroll
        for (int c = 0; c < 4; c++) accO[ni][c] = 0.f;

    // per-thread K/V load coordinates (4 chunks each)
    const int kr = tid >> 4;               // base row 0..15
    const int kc = (tid & 15) << 2;        // col offset 0..60

    for (int t0 = 0; t0 < SEQ; t0 += 64) {
        __syncthreads();   // previous tile's mma reads of sK/sVt complete

        // K tile: rows = keys, cols = dh.  Vt tile: rows = dh, cols = keys.
#pragma unroll
        for (int i = 0; i < 4; i++) {
            int r = kr + i * 16;
            uint32_t off = (uint32_t)(r * ASTR + kc) * 4u;
            CP_ASYNC16(sKu + off,
                       &K[(rowbase + t0 + r) * DIM + colbase + kc]);
            CP_ASYNC16(sVtu + off,
                       &Vt[((size_t)bh * HDIM + r) * SEQ + t0 + kc]);
        }
        CP_COMMIT();
        CP_WAIT(0);
        __syncthreads();

        // ---- S = Qs @ K^T (already includes softmax scale, exp2 domain) ----
        float sfr[8][4];
#pragma unroll
        for (int ni = 0; ni < 8; ni++)
#pragma unroll
            for (int c = 0; c < 4; c++) sfr[ni][c] = 0.f;

#pragma unroll
        for (int ks = 0; ks < 8; ks++) {
            const int k0 = ks * 8;
            uint32_t af[4];
            af[0] = __float_as_uint(sQ[(wm + g)     * ASTR + k0 + t]);
            af[1] = __float_as_uint(sQ[(wm + g + 8) * ASTR + k0 + t]);
            af[2] = __float_as_uint(sQ[(wm + g)     * ASTR + k0 + t + 4]);
            af[3] = __float_as_uint(sQ[(wm + g + 8) * ASTR + k0 + t + 4]);
#pragma unroll
            for (int ni = 0; ni < 8; ni++) {
                uint32_t bf[2];
                const int n = ni * 8 + g;
                bf[0] = __float_as_uint(sK[n * ASTR + k0 + t]);
                bf[1] = __float_as_uint(sK[n * ASTR + k0 + t + 4]);
                mma_tf32(sfr[ni], af, bf);
            }
        }

        // ---- online softmax (rows wm+g and wm+g+8) ----
        float mt0 = sfr[0][0], mt1 = sfr[0][2];
#pragma unroll
        for (int ni = 0; ni < 8; ni++) {
            mt0 = fmaxf(mt0, fmaxf(sfr[ni][0], sfr[ni][1]));
            mt1 = fmaxf(mt1, fmaxf(sfr[ni][2], sfr[ni][3]));
        }
        mt0 = fmaxf(mt0, __shfl_xor_sync(0xffffffffu, mt0, 1));
        mt0 = fmaxf(mt0, __shfl_xor_sync(0xffffffffu, mt0, 2));
        mt1 = fmaxf(mt1, __shfl_xor_sync(0xffffffffu, mt1, 1));
        mt1 = fmaxf(mt1, __shfl_xor_sync(0xffffffffu, mt1, 2));

        const float mn0 = fmaxf(m0, mt0);
        const float mn1 = fmaxf(m1, mt1);
        const float al0 = ex2f(m0 - mn0);
        const float al1 = ex2f(m1 - mn1);
        m0 = mn0; m1 = mn1;

        float lt0 = 0.f, lt1 = 0.f;
#pragma unroll
        for (int ni = 0; ni < 8; ni++) {
            float p0 = ex2f(sfr[ni][0] - mn0);
            float p1 = ex2f(sfr[ni][1] - mn0);
            float p2 = ex2f(sfr[ni][2] - mn1);
            float p3 = ex2f(sfr[ni][3] - mn1);
            lt0 += p0 + p1;
            lt1 += p2 + p3;
            float2 w0 = make_float2(f2tf32(p0), f2tf32(p1));
            float2 w1 = make_float2(f2tf32(p2), f2tf32(p3));
            *reinterpret_cast<float2*>(&sP[(wm + g)     * ASTR + ni * 8 + 2 * t]) = w0;
            *reinterpret_cast<float2*>(&sP[(wm + g + 8) * ASTR + ni * 8 + 2 * t]) = w1;
        }
        lt0 += __shfl_xor_sync(0xffffffffu, lt0, 1);
        lt0 += __shfl_xor_sync(0xffffffffu, lt0, 2);
        lt1 += __shfl_xor_sync(0xffffffffu, lt1, 1);
        lt1 += __shfl_xor_sync(0xffffffffu, lt1, 2);
        l0 = l0 * al0 + lt0;
        l1 = l1 * al1 + lt1;

#pragma unroll
        for (int ni = 0; ni < 8; ni++) {
            accO[ni][0] *= al0; accO[ni][1] *= al0;
            accO[ni][2] *= al1; accO[ni][3] *= al1;
        }
        __syncwarp();   // sP produced/consumed within the same warp

        // ---- O += P @ V ----
#pragma unroll
        for (int ks = 0; ks < 8; ks++) {
            const int k0 = ks * 8;
            uint32_t pf[4];
            pf[0] = __float_as_uint(sP[(wm + g)     * ASTR + k0 + t]);
            pf[1] = __float_as_uint(sP[(wm + g + 8) * ASTR + k0 + t]);
            pf[2] = __float_as_uint(sP[(wm + g)     * ASTR + k0 + t + 4]);
            pf[3] = __float_as_uint(sP[(wm + g + 8) * ASTR + k0 + t + 4]);
#pragma unroll
            for (int ni = 0; ni < 8; ni++) {
                uint32_t bf[2];
                const int n = ni * 8 + g;
                bf[0] = __float_as_uint(sVt[n * ASTR + k0 + t]);
                bf[1] = __float_as_uint(sVt[n * ASTR + k0 + t + 4]);
                mma_tf32(accO[ni], pf, bf);
            }
        }
    }

    // ---- normalize + write ctx (tf32-rounded: feeds the Wo tf32 GEMM) ----
    const float inv0 = 1.f / l0;
    const float inv1 = 1.f / l1;
#pragma unroll
    for (int ni = 0; ni < 8; ni++) {
        const int col = colbase + ni * 8 + 2 * t;
        float2 o0, o1;
        o0.x = f2tf32(accO[ni][0] * inv0);
        o0.y = f2tf32(accO[ni][1] * inv0);
        o1.x = f2tf32(accO[ni][2] * inv1);
        o1.y = f2tf32(accO[ni][3] * inv1);
        *reinterpret_cast<float2*>(
            &O[(rowbase + q0 + wm + g) * DIM + col]) = o0;
        *reinterpret_cast<float2*>(
            &O[(rowbase + q0 + wm + g + 8) * DIM + col]) = o1;
    }
}

// ===========================================================================
extern "C" void kernel_launch(void* const* d_in, const int* in_sizes, int n_in,
                              void* d_out, int out_size)
{
    const float* x  = (const float*)d_in[0];
    const float* Wq = (const float*)d_in[1];
    const float* bq = (const float*)d_in[2];
    const float* Wk = (const float*)d_in[3];
    const float* bk = (const float*)d_in[4];
    const float* Wv = (const float*)d_in[5];
    const float* bv = (const float*)d_in[6];
    const float* Wo = (const float*)d_in[7];
    const float* bo = (const float*)d_in[8];
    float* out = (float*)d_out;

    float *q, *k, *v, *vt, *ctx, *xr, *wt;
    cudaGetSymbolAddress((void**)&q,   g_q);
    cudaGetSymbolAddress((void**)&k,   g_k);
    cudaGetSymbolAddress((void**)&v,   g_v);
    cudaGetSymbolAddress((void**)&vt,  g_vt);
    cudaGetSymbolAddress((void**)&ctx, g_ctx);
    cudaGetSymbolAddress((void**)&xr,  g_xr);
    cudaGetSymbolAddress((void**)&wt,  g_wt);
    float* wtq = wt;
    float* wtk = wt + DIM * DIM;
    float* wtv = wt + 2 * DIM * DIM;
    float* wto = wt + 3 * DIM * DIM;

    // 1) round x to tf32
    {
        int n4 = NTOK * DIM / 4;
        round_tf32_kernel<<<(n4 + 255) / 256, 256>>>(
            (const float4*)x, (float4*)xr, n4);
    }
    // 2) transpose + round weights
    {
        dim3 tb(32, 8), tg(DIM / 32, DIM / 32);
        transpose_round_kernel<<<tg, tb>>>(Wq, wtq);
        transpose_round_kernel<<<tg, tb>>>(Wk, wtk);
        transpose_round_kernel<<<tg, tb>>>(Wv, wtv);
        transpose_round_kernel<<<tg, tb>>>(Wo, wto);
    }

    // 3) QKV projections (rounded outputs: they feed tf32 attention mma)
    cudaFuncSetAttribute(gemm_mma_kernel,
                         cudaFuncAttributeMaxDynamicSharedMemorySize,
                         GEMM_SMEM_BYTES);
    dim3 gg(GN / 128, NTOK / 128);
    gemm_mma_kernel<<<gg, 256, GEMM_SMEM_BYTES>>>(xr, wtq, bq, q, 1);
    gemm_mma_kernel<<<gg, 256, GEMM_SMEM_BYTES>>>(xr, wtk, bk, k, 1);
    gemm_mma_kernel<<<gg, 256, GEMM_SMEM_BYTES>>>(xr, wtv, bv, v, 1);

    // 4) transpose V for the PV mma B-operand
    {
        dim3 tb(32, 8), tg(SEQ / 32, HDIM / 32, BATCH * HEADS);
        vt_transpose_kernel<<<tg, tb>>>(v, vt);
    }

    // 5) attention (mma.sync tf32 flash)
    cudaFuncSetAttribute(attn_mma_kernel,
                         cudaFuncAttributeMaxDynamicSharedMemorySize,
                         ATTN_SMEM_BYTES);
    attn_mma_kernel<<<dim3(SEQ / 128, HEADS, BATCH), 256, ATTN_SMEM_BYTES>>>(
        q, k, vt, ctx);

    // 6) output projection (fp32 output, no rounding)
    gemm_mma_kernel<<<gg, 256, GEMM_SMEM_BYTES>>>(ctx, wto, bo, out, 0);
}